// round 3
// baseline (speedup 1.0000x reference)
#include <cuda_runtime.h>
#include <cstdint>

// ---------------------------------------------------------------------------
// RGCN 2-layer, N=1e6 nodes, E=16e6 edges, 3 relations, C: 3 -> 2 -> 2.
//
//   k_init  : clear accumulators, pad x[N,3] -> float4[N], detect index width
//   k_edge1 : per edge: gather x4[src], red.v4 {x0,x1,x2,1} -> acc1[dst*3+rel]
//   k_node1 : h = relu(x@root1 + b1 + sum_r (acc1_r.xyz/max(cnt,1)) @ W1[r])
//   k_edge2 : per edge: gather h[src],  red.v2 {h0,h1}     -> acc2[dst*3+rel]
//   k_node2 : out = h@root2 + b2 + sum_r (acc2_r/max(cnt,1)) @ W2[r]
//
// mean(xs@W) == mean(xs)@W  =>  edge kernels carry NO matmul work, exactly
// ONE vector reduction per edge; counts reused across layers.
// Robustness: inputs identified by element count; index dtype (int64 vs
// int32) auto-detected on device; all edge indices bounds-checked.
// ---------------------------------------------------------------------------

#define NN_MAX 1000000
#define NR 3

__device__ float4 g_acc1[NN_MAX * NR];   // (sum_x0, sum_x1, sum_x2, count)
__device__ float2 g_acc2[NN_MAX * NR];   // (sum_h0, sum_h1)
__device__ float4 g_x4[NN_MAX];          // padded input features
__device__ float2 g_h[NN_MAX];           // layer-1 activations
__device__ int    g_is32;                // 1 if edge indices are 32-bit

__device__ __forceinline__ void red_add_v4(float4* p, float a, float b, float c, float d) {
    asm volatile("red.global.add.v4.f32 [%0], {%1, %2, %3, %4};"
                 :: "l"(p), "f"(a), "f"(b), "f"(c), "f"(d) : "memory");
}
__device__ __forceinline__ void red_add_v2(float2* p, float a, float b) {
    asm volatile("red.global.add.v2.f32 [%0], {%1, %2};"
                 :: "l"(p), "f"(a), "f"(b) : "memory");
}

__global__ void k_init(const float* __restrict__ x, const void* __restrict__ ea,
                       int n, int ne) {
    int i = blockIdx.x * blockDim.x + threadIdx.x;
    if (i == 0) {
        // Detect index width from edge_attr: int64 relation ids are all in
        // [0, NR). If the buffer is really int32, an int64 read is valid only
        // with prob 1/3 per pair -> (1/3)^64 false-negative rate over 64 reads.
        const long long* p = (const long long*)ea;
        int m = ne < 64 ? ne : 64;   // reading m int64 is in-bounds either way
        int is32 = 0;
        for (int j = 0; j < m; j++) {
            long long v = p[j];
            if (v < 0 || v >= NR) { is32 = 1; break; }
        }
        g_is32 = is32;
    }
    if (i < n) {
        g_x4[i] = make_float4(x[3*i], x[3*i+1], x[3*i+2], 0.f);
        #pragma unroll
        for (int r = 0; r < NR; r++) {
            g_acc1[i*NR + r] = make_float4(0.f, 0.f, 0.f, 0.f);
            g_acc2[i*NR + r] = make_float2(0.f, 0.f);
        }
    }
}

// ---- edge bodies (4 edges/thread, gathers batched before reductions) ------

template <typename T>
__device__ __forceinline__ void edge1_body(const T* __restrict__ src,
                                           const T* __restrict__ dst,
                                           const T* __restrict__ rel,
                                           long long e0, long long ne, unsigned nu) {
    unsigned s[4], d[4], r[4];
    bool ok[4];
    #pragma unroll
    for (int j = 0; j < 4; j++) {
        long long e = e0 + j;
        bool in = e < ne;
        s[j] = in ? (unsigned)src[e] : 0u;
        d[j] = in ? (unsigned)dst[e] : 0u;
        r[j] = in ? (unsigned)rel[e] : 0u;
        ok[j] = in && (s[j] < nu) && (d[j] < nu) && (r[j] < (unsigned)NR);
    }
    float4 xs[4];
    #pragma unroll
    for (int j = 0; j < 4; j++)
        xs[j] = ok[j] ? g_x4[s[j]] : make_float4(0.f, 0.f, 0.f, 0.f);
    #pragma unroll
    for (int j = 0; j < 4; j++)
        if (ok[j])
            red_add_v4(&g_acc1[d[j]*NR + r[j]], xs[j].x, xs[j].y, xs[j].z, 1.0f);
}

template <typename T>
__device__ __forceinline__ void edge2_body(const T* __restrict__ src,
                                           const T* __restrict__ dst,
                                           const T* __restrict__ rel,
                                           long long e0, long long ne, unsigned nu) {
    unsigned s[4], d[4], r[4];
    bool ok[4];
    #pragma unroll
    for (int j = 0; j < 4; j++) {
        long long e = e0 + j;
        bool in = e < ne;
        s[j] = in ? (unsigned)src[e] : 0u;
        d[j] = in ? (unsigned)dst[e] : 0u;
        r[j] = in ? (unsigned)rel[e] : 0u;
        ok[j] = in && (s[j] < nu) && (d[j] < nu) && (r[j] < (unsigned)NR);
    }
    float2 hs[4];
    #pragma unroll
    for (int j = 0; j < 4; j++)
        hs[j] = ok[j] ? g_h[s[j]] : make_float2(0.f, 0.f);
    #pragma unroll
    for (int j = 0; j < 4; j++)
        if (ok[j])
            red_add_v2(&g_acc2[d[j]*NR + r[j]], hs[j].x, hs[j].y);
}

__global__ void k_edge1(const void* __restrict__ ei, const void* __restrict__ ea,
                        int ne, int n) {
    long long e0 = (long long)(blockIdx.x * (long long)blockDim.x + threadIdx.x) * 4;
    if (e0 >= ne) return;
    unsigned nu = (unsigned)n;
    if (g_is32) {
        const int* e = (const int*)ei;
        edge1_body<int>(e, e + ne, (const int*)ea, e0, ne, nu);
    } else {
        const long long* e = (const long long*)ei;
        edge1_body<long long>(e, e + ne, (const long long*)ea, e0, ne, nu);
    }
}

__global__ void k_edge2(const void* __restrict__ ei, const void* __restrict__ ea,
                        int ne, int n) {
    long long e0 = (long long)(blockIdx.x * (long long)blockDim.x + threadIdx.x) * 4;
    if (e0 >= ne) return;
    unsigned nu = (unsigned)n;
    if (g_is32) {
        const int* e = (const int*)ei;
        edge2_body<int>(e, e + ne, (const int*)ea, e0, ne, nu);
    } else {
        const long long* e = (const long long*)ei;
        edge2_body<long long>(e, e + ne, (const long long*)ea, e0, ne, nu);
    }
}

// ---- node kernels ---------------------------------------------------------

__global__ void k_node1(const float* __restrict__ W1, const float* __restrict__ root1,
                        const float* __restrict__ b1, int n) {
    int v = blockIdx.x * blockDim.x + threadIdx.x;
    if (v >= n) return;
    float4 xs = g_x4[v];
    float h0 = b1[0] + xs.x*root1[0] + xs.y*root1[2] + xs.z*root1[4];
    float h1 = b1[1] + xs.x*root1[1] + xs.y*root1[3] + xs.z*root1[5];
    #pragma unroll
    for (int r = 0; r < NR; r++) {
        float4 a = g_acc1[v*NR + r];
        float inv = 1.0f / fmaxf(a.w, 1.0f);
        float mx = a.x*inv, my = a.y*inv, mz = a.z*inv;
        h0 += mx*W1[(r*3+0)*2+0] + my*W1[(r*3+1)*2+0] + mz*W1[(r*3+2)*2+0];
        h1 += mx*W1[(r*3+0)*2+1] + my*W1[(r*3+1)*2+1] + mz*W1[(r*3+2)*2+1];
    }
    g_h[v] = make_float2(fmaxf(h0, 0.f), fmaxf(h1, 0.f));
}

__global__ void k_node2(const float* __restrict__ W2, const float* __restrict__ root2,
                        const float* __restrict__ b2, float2* __restrict__ out, int n) {
    int v = blockIdx.x * blockDim.x + threadIdx.x;
    if (v >= n) return;
    float2 h = g_h[v];
    float o0 = b2[0] + h.x*root2[0] + h.y*root2[2];
    float o1 = b2[1] + h.x*root2[1] + h.y*root2[3];
    #pragma unroll
    for (int r = 0; r < NR; r++) {
        float2 s = g_acc2[v*NR + r];
        float c  = g_acc1[v*NR + r].w;
        float inv = 1.0f / fmaxf(c, 1.0f);
        float m0 = s.x*inv, m1 = s.y*inv;
        o0 += m0*W2[(r*2+0)*2+0] + m1*W2[(r*2+1)*2+0];
        o1 += m0*W2[(r*2+0)*2+1] + m1*W2[(r*2+1)*2+1];
    }
    out[v] = make_float2(o0, o1);
}

// ---- host -----------------------------------------------------------------

extern "C" void kernel_launch(void* const* d_in, const int* in_sizes, int n_in,
                              void* d_out, int out_size) {
    // Identify inputs by element count (robust to metadata ordering).
    int ix = -1, iei = -1, iea = -1, iW1 = -1, ir1 = -1, ib1 = -1,
        iW2 = -1, ir2 = -1, ib2 = -1;
    // Large arrays: largest = edge_index(2E), 2nd = edge_attr(E), 3rd = x(3N).
    int big[3] = {-1, -1, -1};  // indices sorted by size desc
    for (int i = 0; i < n_in; i++) {
        int s = in_sizes[i];
        if (s == 18) iW1 = i;
        else if (s == 6)  ir1 = i;
        else if (s == 12) iW2 = i;
        else if (s == 4)  ir2 = i;
        else if (s == 2)  { if (ib1 < 0) ib1 = i; else ib2 = i; }
        else if (s > 1000) {
            int j = i;
            for (int k = 0; k < 3; k++) {
                if (big[k] < 0 || in_sizes[j] > in_sizes[big[k]]) {
                    int t = big[k]; big[k] = j; j = t;
                    if (j < 0) break;
                }
            }
        }
    }
    iei = big[0]; iea = big[1]; ix = big[2];
    // Positional fallback (setup_inputs order) if identification failed.
    if (ix < 0 || iei < 0 || iea < 0 || iW1 < 0 || ir1 < 0 || ib1 < 0 ||
        iW2 < 0 || ir2 < 0 || ib2 < 0) {
        ix = 0; iei = 1; iea = 2; iW1 = 3; ir1 = 4; ib1 = 5; iW2 = 6; ir2 = 7; ib2 = 8;
    }

    const float* x     = (const float*)d_in[ix];
    const void*  ei    = d_in[iei];
    const void*  ea    = d_in[iea];
    const float* W1    = (const float*)d_in[iW1];
    const float* root1 = (const float*)d_in[ir1];
    const float* b1    = (const float*)d_in[ib1];
    const float* W2    = (const float*)d_in[iW2];
    const float* root2 = (const float*)d_in[ir2];
    const float* b2    = (const float*)d_in[ib2];

    int n  = in_sizes[ix] / 3;
    if (n > NN_MAX) n = NN_MAX;          // defensive clamp (scratch capacity)
    int ne = in_sizes[iei] / 2;

    const int threads = 256;
    int nb  = (n + threads - 1) / threads;
    int et  = (ne + 3) / 4;              // 4 edges per thread
    int eb  = (et + threads - 1) / threads;

    k_init <<<nb, threads>>>(x, ea, n, ne);
    k_edge1<<<eb, threads>>>(ei, ea, ne, n);
    k_node1<<<nb, threads>>>(W1, root1, b1, n);
    k_edge2<<<eb, threads>>>(ei, ea, ne, n);
    k_node2<<<nb, threads>>>(W2, root2, b2, (float2*)d_out, n);
}

// round 8
// speedup vs baseline: 1.0157x; 1.0157x over previous
#include <cuda_runtime.h>
#include <cstdint>

// ---------------------------------------------------------------------------
// RGCN 2-layer, N=1e6 nodes, E=16e6 edges, 3 relations, C: 3 -> 2 -> 2.
//
//   k_init  : detect index width, pad x[N,3] -> float4[N], zero acc1
//   k_edge1 : per edge: gather x4[src], red.v4 {x0,x1,x2,1} -> acc1[dst*3+rel]
//   k_node1 : h = relu(x@root1 + b1 + sum_r mean_r @ W1[r]);
//             also writes g_inv (1/max(cnt,1)) and zeroes acc2
//   k_edge2 : per edge: gather h[src],  red.v2 {h0,h1}     -> acc2[dst*3+rel]
//   k_node2 : out = h@root2 + b2 + sum_r (acc2_r * inv_r) @ W2[r]
//
// mean(xs@W) == mean(xs)@W  =>  edge kernels carry NO matmul work, exactly
// ONE vector reduction per edge; counts computed once, reused across layers.
// Edge kernels are LTS(L2)-throughput bound: 1 gather sector + 1 RED sector
// per edge is the structural minimum for scatter aggregation. Index arrays
// are read with 16B vector loads (4 edges/thread) to minimize L1 wavefronts.
// ---------------------------------------------------------------------------

#define NN_MAX 1000000
#define NR 3

__device__ float4 g_acc1[NN_MAX * NR];   // (sum_x0, sum_x1, sum_x2, count)
__device__ float2 g_acc2[NN_MAX * NR];   // (sum_h0, sum_h1)
__device__ float  g_inv [NN_MAX * NR];   // 1 / max(count, 1)
__device__ float4 g_x4[NN_MAX];          // padded input features
__device__ float2 g_h[NN_MAX];           // layer-1 activations
__device__ int    g_is32;                // 1 if edge indices are 32-bit

__device__ __forceinline__ void red_add_v4(float4* p, float a, float b, float c, float d) {
    asm volatile("red.global.add.v4.f32 [%0], {%1, %2, %3, %4};"
                 :: "l"(p), "f"(a), "f"(b), "f"(c), "f"(d) : "memory");
}
__device__ __forceinline__ void red_add_v2(float2* p, float a, float b) {
    asm volatile("red.global.add.v2.f32 [%0], {%1, %2};"
                 :: "l"(p), "f"(a), "f"(b) : "memory");
}

__global__ void k_init(const float* __restrict__ x, const void* __restrict__ ea,
                       int n, int ne) {
    int i = blockIdx.x * blockDim.x + threadIdx.x;
    if (i == 0) {
        // Detect index width from edge_attr: true int64 relation ids are all
        // in [0, NR). If the buffer is really int32, an int64 read passes the
        // test only with prob ~1/3 per pair -> (1/3)^64 false-negative rate.
        const long long* p = (const long long*)ea;
        int m = ne < 64 ? ne : 64;   // reading m int64 is in-bounds either way
        int is32 = 0;
        for (int j = 0; j < m; j++) {
            long long v = p[j];
            if (v < 0 || v >= NR) { is32 = 1; break; }
        }
        g_is32 = is32;
    }
    if (i < n) {
        g_x4[i] = make_float4(x[3*i], x[3*i+1], x[3*i+2], 0.f);
        #pragma unroll
        for (int r = 0; r < NR; r++)
            g_acc1[i*NR + r] = make_float4(0.f, 0.f, 0.f, 0.f);
    }
}

// ---- edge kernels: 4 edges/thread, 16B vector index loads -----------------

__global__ void __launch_bounds__(256) k_edge1(const void* __restrict__ ei,
                                               const void* __restrict__ ea,
                                               int ne, int n) {
    long long e0 = (long long)(blockIdx.x * (long long)blockDim.x + threadIdx.x) * 4;
    if (e0 >= ne) return;
    const unsigned nu = (unsigned)n;

    unsigned s[4], d[4], r[4];
    if (e0 + 4 <= ne) {
        if (g_is32) {
            const int* src = (const int*)ei;
            const int* dst = src + ne;
            const int* rel = (const int*)ea;
            int4 sv = *(const int4*)(src + e0);
            int4 dv = *(const int4*)(dst + e0);
            int4 rv = *(const int4*)(rel + e0);
            s[0]=(unsigned)sv.x; s[1]=(unsigned)sv.y; s[2]=(unsigned)sv.z; s[3]=(unsigned)sv.w;
            d[0]=(unsigned)dv.x; d[1]=(unsigned)dv.y; d[2]=(unsigned)dv.z; d[3]=(unsigned)dv.w;
            r[0]=(unsigned)rv.x; r[1]=(unsigned)rv.y; r[2]=(unsigned)rv.z; r[3]=(unsigned)rv.w;
        } else {
            const long long* src = (const long long*)ei;
            const long long* dst = src + ne;
            const long long* rel = (const long long*)ea;
            ulonglong2 s01 = *(const ulonglong2*)(src + e0);
            ulonglong2 s23 = *(const ulonglong2*)(src + e0 + 2);
            ulonglong2 d01 = *(const ulonglong2*)(dst + e0);
            ulonglong2 d23 = *(const ulonglong2*)(dst + e0 + 2);
            ulonglong2 r01 = *(const ulonglong2*)(rel + e0);
            ulonglong2 r23 = *(const ulonglong2*)(rel + e0 + 2);
            s[0]=(unsigned)s01.x; s[1]=(unsigned)s01.y; s[2]=(unsigned)s23.x; s[3]=(unsigned)s23.y;
            d[0]=(unsigned)d01.x; d[1]=(unsigned)d01.y; d[2]=(unsigned)d23.x; d[3]=(unsigned)d23.y;
            r[0]=(unsigned)r01.x; r[1]=(unsigned)r01.y; r[2]=(unsigned)r23.x; r[3]=(unsigned)r23.y;
        }
        bool ok[4];
        float4 xs[4];
        #pragma unroll
        for (int j = 0; j < 4; j++) {
            ok[j] = (s[j] < nu) && (d[j] < nu) && (r[j] < (unsigned)NR);
            xs[j] = ok[j] ? g_x4[s[j]] : make_float4(0.f, 0.f, 0.f, 0.f);
        }
        #pragma unroll
        for (int j = 0; j < 4; j++)
            if (ok[j])
                red_add_v4(&g_acc1[d[j]*NR + r[j]], xs[j].x, xs[j].y, xs[j].z, 1.0f);
    } else {
        for (long long e = e0; e < ne; e++) {
            unsigned ss, dd, rr;
            if (g_is32) {
                const int* src = (const int*)ei;
                ss = (unsigned)src[e]; dd = (unsigned)src[ne + e];
                rr = (unsigned)((const int*)ea)[e];
            } else {
                const long long* src = (const long long*)ei;
                ss = (unsigned)src[e]; dd = (unsigned)src[ne + e];
                rr = (unsigned)((const long long*)ea)[e];
            }
            if (ss < nu && dd < nu && rr < (unsigned)NR) {
                float4 xs = g_x4[ss];
                red_add_v4(&g_acc1[dd*NR + rr], xs.x, xs.y, xs.z, 1.0f);
            }
        }
    }
}

__global__ void __launch_bounds__(256) k_edge2(const void* __restrict__ ei,
                                               const void* __restrict__ ea,
                                               int ne, int n) {
    long long e0 = (long long)(blockIdx.x * (long long)blockDim.x + threadIdx.x) * 4;
    if (e0 >= ne) return;
    const unsigned nu = (unsigned)n;

    unsigned s[4], d[4], r[4];
    if (e0 + 4 <= ne) {
        if (g_is32) {
            const int* src = (const int*)ei;
            const int* dst = src + ne;
            const int* rel = (const int*)ea;
            int4 sv = *(const int4*)(src + e0);
            int4 dv = *(const int4*)(dst + e0);
            int4 rv = *(const int4*)(rel + e0);
            s[0]=(unsigned)sv.x; s[1]=(unsigned)sv.y; s[2]=(unsigned)sv.z; s[3]=(unsigned)sv.w;
            d[0]=(unsigned)dv.x; d[1]=(unsigned)dv.y; d[2]=(unsigned)dv.z; d[3]=(unsigned)dv.w;
            r[0]=(unsigned)rv.x; r[1]=(unsigned)rv.y; r[2]=(unsigned)rv.z; r[3]=(unsigned)rv.w;
        } else {
            const long long* src = (const long long*)ei;
            const long long* dst = src + ne;
            const long long* rel = (const long long*)ea;
            ulonglong2 s01 = *(const ulonglong2*)(src + e0);
            ulonglong2 s23 = *(const ulonglong2*)(src + e0 + 2);
            ulonglong2 d01 = *(const ulonglong2*)(dst + e0);
            ulonglong2 d23 = *(const ulonglong2*)(dst + e0 + 2);
            ulonglong2 r01 = *(const ulonglong2*)(rel + e0);
            ulonglong2 r23 = *(const ulonglong2*)(rel + e0 + 2);
            s[0]=(unsigned)s01.x; s[1]=(unsigned)s01.y; s[2]=(unsigned)s23.x; s[3]=(unsigned)s23.y;
            d[0]=(unsigned)d01.x; d[1]=(unsigned)d01.y; d[2]=(unsigned)d23.x; d[3]=(unsigned)d23.y;
            r[0]=(unsigned)r01.x; r[1]=(unsigned)r01.y; r[2]=(unsigned)r23.x; r[3]=(unsigned)r23.y;
        }
        bool ok[4];
        float2 hs[4];
        #pragma unroll
        for (int j = 0; j < 4; j++) {
            ok[j] = (s[j] < nu) && (d[j] < nu) && (r[j] < (unsigned)NR);
            hs[j] = ok[j] ? g_h[s[j]] : make_float2(0.f, 0.f);
        }
        #pragma unroll
        for (int j = 0; j < 4; j++)
            if (ok[j])
                red_add_v2(&g_acc2[d[j]*NR + r[j]], hs[j].x, hs[j].y);
    } else {
        for (long long e = e0; e < ne; e++) {
            unsigned ss, dd, rr;
            if (g_is32) {
                const int* src = (const int*)ei;
                ss = (unsigned)src[e]; dd = (unsigned)src[ne + e];
                rr = (unsigned)((const int*)ea)[e];
            } else {
                const long long* src = (const long long*)ei;
                ss = (unsigned)src[e]; dd = (unsigned)src[ne + e];
                rr = (unsigned)((const long long*)ea)[e];
            }
            if (ss < nu && dd < nu && rr < (unsigned)NR) {
                float2 hh = g_h[ss];
                red_add_v2(&g_acc2[dd*NR + rr], hh.x, hh.y);
            }
        }
    }
}

// ---- node kernels ---------------------------------------------------------

__global__ void k_node1(const float* __restrict__ W1, const float* __restrict__ root1,
                        const float* __restrict__ b1, int n) {
    int v = blockIdx.x * blockDim.x + threadIdx.x;
    if (v >= n) return;
    float4 xs = g_x4[v];
    float h0 = b1[0] + xs.x*root1[0] + xs.y*root1[2] + xs.z*root1[4];
    float h1 = b1[1] + xs.x*root1[1] + xs.y*root1[3] + xs.z*root1[5];
    #pragma unroll
    for (int r = 0; r < NR; r++) {
        float4 a = g_acc1[v*NR + r];
        float inv = 1.0f / fmaxf(a.w, 1.0f);
        float mx = a.x*inv, my = a.y*inv, mz = a.z*inv;
        h0 += mx*W1[(r*3+0)*2+0] + my*W1[(r*3+1)*2+0] + mz*W1[(r*3+2)*2+0];
        h1 += mx*W1[(r*3+0)*2+1] + my*W1[(r*3+1)*2+1] + mz*W1[(r*3+2)*2+1];
        g_inv[v*NR + r]  = inv;                       // counts for layer 2
        g_acc2[v*NR + r] = make_float2(0.f, 0.f);     // fused acc2 zeroing
    }
    g_h[v] = make_float2(fmaxf(h0, 0.f), fmaxf(h1, 0.f));
}

__global__ void k_node2(const float* __restrict__ W2, const float* __restrict__ root2,
                        const float* __restrict__ b2, float2* __restrict__ out, int n) {
    int v = blockIdx.x * blockDim.x + threadIdx.x;
    if (v >= n) return;
    float2 h = g_h[v];
    float o0 = b2[0] + h.x*root2[0] + h.y*root2[2];
    float o1 = b2[1] + h.x*root2[1] + h.y*root2[3];
    #pragma unroll
    for (int r = 0; r < NR; r++) {
        float2 s  = g_acc2[v*NR + r];
        float inv = g_inv[v*NR + r];
        float m0 = s.x*inv, m1 = s.y*inv;
        o0 += m0*W2[(r*2+0)*2+0] + m1*W2[(r*2+1)*2+0];
        o1 += m0*W2[(r*2+0)*2+1] + m1*W2[(r*2+1)*2+1];
    }
    out[v] = make_float2(o0, o1);
}

// ---- host -----------------------------------------------------------------

extern "C" void kernel_launch(void* const* d_in, const int* in_sizes, int n_in,
                              void* d_out, int out_size) {
    // Identify inputs by element count (robust to metadata ordering).
    int ix = -1, iei = -1, iea = -1, iW1 = -1, ir1 = -1, ib1 = -1,
        iW2 = -1, ir2 = -1, ib2 = -1;
    int big[3] = {-1, -1, -1};  // largest three arrays, size-descending
    for (int i = 0; i < n_in; i++) {
        int s = in_sizes[i];
        if (s == 18) iW1 = i;
        else if (s == 6)  ir1 = i;
        else if (s == 12) iW2 = i;
        else if (s == 4)  ir2 = i;
        else if (s == 2)  { if (ib1 < 0) ib1 = i; else ib2 = i; }
        else if (s > 1000) {
            int j = i;
            for (int k = 0; k < 3; k++) {
                if (big[k] < 0 || in_sizes[j] > in_sizes[big[k]]) {
                    int t = big[k]; big[k] = j; j = t;
                    if (j < 0) break;
                }
            }
        }
    }
    iei = big[0]; iea = big[1]; ix = big[2];
    if (ix < 0 || iei < 0 || iea < 0 || iW1 < 0 || ir1 < 0 || ib1 < 0 ||
        iW2 < 0 || ir2 < 0 || ib2 < 0) {   // positional fallback
        ix = 0; iei = 1; iea = 2; iW1 = 3; ir1 = 4; ib1 = 5; iW2 = 6; ir2 = 7; ib2 = 8;
    }

    const float* x     = (const float*)d_in[ix];
    const void*  ei    = d_in[iei];
    const void*  ea    = d_in[iea];
    const float* W1    = (const float*)d_in[iW1];
    const float* root1 = (const float*)d_in[ir1];
    const float* b1    = (const float*)d_in[ib1];
    const float* W2    = (const float*)d_in[iW2];
    const float* root2 = (const float*)d_in[ir2];
    const float* b2    = (const float*)d_in[ib2];

    int n  = in_sizes[ix] / 3;
    if (n > NN_MAX) n = NN_MAX;          // defensive clamp (scratch capacity)
    int ne = in_sizes[iei] / 2;

    const int threads = 256;
    int nb = (n + threads - 1) / threads;
    int et = (ne + 3) / 4;               // 4 edges per thread
    int eb = (et + threads - 1) / threads;

    k_init <<<nb, threads>>>(x, ea, n, ne);
    k_edge1<<<eb, threads>>>(ei, ea, ne, n);
    k_node1<<<nb, threads>>>(W1, root1, b1, n);
    k_edge2<<<eb, threads>>>(ei, ea, ne, n);
    k_node2<<<nb, threads>>>(W2, root2, b2, (float2*)d_out, n);
}

// round 11
// speedup vs baseline: 1.0348x; 1.0188x over previous
#include <cuda_runtime.h>
#include <cstdint>

// ---------------------------------------------------------------------------
// RGCN 2-layer, N=1e6 nodes, E=16e6 edges, 3 relations, C: 3 -> 2 -> 2.
//
//   k_init  : detect index width (1 warp, ballot), pad x -> float4, zero acc1
//   k_edge1 : per edge: gather x4[src], red.v4 {x0,x1,x2,1} -> acc1[dst*3+rel]
//   k_node1 : h = relu(x@root1 + b1 + sum_r mean_r @ W1[r]);
//             writes g_inv (1/max(cnt,1)) and zeroes acc2
//   k_edge2 : per edge: gather h[src],  red.v2 {h0,h1}     -> acc2[dst*3+rel]
//   k_node2 : out = h@root2 + b2 + sum_r (acc2_r * inv_r) @ W2[r]
//
// mean(xs@W) == mean(xs)@W  =>  edge kernels carry NO matmul work, exactly
// ONE vector reduction per edge; counts computed once, reused across layers.
// Edge kernels are at the L1-wavefront / L2-sector co-limit (~2 divergent
// ops x 32B sectors per edge) -- the structural floor for scatter aggregation.
// ---------------------------------------------------------------------------

#define NN_MAX 1000000
#define NR 3

__device__ float4 g_acc1[NN_MAX * NR];   // (sum_x0, sum_x1, sum_x2, count)
__device__ float2 g_acc2[NN_MAX * NR];   // (sum_h0, sum_h1)
__device__ float  g_inv [NN_MAX * NR];   // 1 / max(count, 1)
__device__ float4 g_x4[NN_MAX];          // padded input features
__device__ float2 g_h[NN_MAX];           // layer-1 activations
__device__ int    g_is32;                // 1 if edge indices are 32-bit

__device__ __forceinline__ void red_add_v4(float4* p, float a, float b, float c, float d) {
    asm volatile("red.global.add.v4.f32 [%0], {%1, %2, %3, %4};"
                 :: "l"(p), "f"(a), "f"(b), "f"(c), "f"(d) : "memory");
}
__device__ __forceinline__ void red_add_v2(float2* p, float a, float b) {
    asm volatile("red.global.add.v2.f32 [%0], {%1, %2};"
                 :: "l"(p), "f"(a), "f"(b) : "memory");
}

__global__ void k_init(const float* __restrict__ x, const void* __restrict__ ea,
                       int n, int ne) {
    int i = blockIdx.x * blockDim.x + threadIdx.x;

    // Index-width detection, parallelized over one warp (2 loads/lane, all
    // independent -> ~1 us instead of 64 serial dependent loads ~20 us).
    // True int64 relation ids are all in [0, NR); if the buffer is int32,
    // an int64 read passes only with prob ~1/3 per pair -> (1/3)^64 miss rate.
    if (blockIdx.x == 0 && threadIdx.x < 32) {
        const long long* p = (const long long*)ea;
        int m = ne < 64 ? ne : 64;          // m int64 reads in-bounds either way
        int lane = threadIdx.x;
        bool bad = false;
        if (lane < m)      { long long v = p[lane];      bad |= (v < 0 || v >= NR); }
        if (lane + 32 < m) { long long v = p[lane + 32]; bad |= (v < 0 || v >= NR); }
        unsigned ball = __ballot_sync(0xffffffffu, bad);
        if (lane == 0) g_is32 = (ball != 0u) ? 1 : 0;
    }

    if (i < n) {
        g_x4[i] = make_float4(x[3*i], x[3*i+1], x[3*i+2], 0.f);
        #pragma unroll
        for (int r = 0; r < NR; r++)
            g_acc1[i*NR + r] = make_float4(0.f, 0.f, 0.f, 0.f);
    }
}

// ---- edge kernels: 4 edges/thread, 16B vector index loads -----------------

__global__ void __launch_bounds__(256) k_edge1(const void* __restrict__ ei,
                                               const void* __restrict__ ea,
                                               int ne, int n) {
    long long e0 = (long long)(blockIdx.x * (long long)blockDim.x + threadIdx.x) * 4;
    if (e0 >= ne) return;
    const unsigned nu = (unsigned)n;
    const int is32 = g_is32;

    unsigned s[4], d[4], r[4];
    if (e0 + 4 <= ne) {
        if (is32) {
            const int* src = (const int*)ei;
            const int* dst = src + ne;
            const int* rel = (const int*)ea;
            int4 sv = *(const int4*)(src + e0);
            int4 dv = *(const int4*)(dst + e0);
            int4 rv = *(const int4*)(rel + e0);
            s[0]=(unsigned)sv.x; s[1]=(unsigned)sv.y; s[2]=(unsigned)sv.z; s[3]=(unsigned)sv.w;
            d[0]=(unsigned)dv.x; d[1]=(unsigned)dv.y; d[2]=(unsigned)dv.z; d[3]=(unsigned)dv.w;
            r[0]=(unsigned)rv.x; r[1]=(unsigned)rv.y; r[2]=(unsigned)rv.z; r[3]=(unsigned)rv.w;
        } else {
            const long long* src = (const long long*)ei;
            const long long* dst = src + ne;
            const long long* rel = (const long long*)ea;
            ulonglong2 s01 = *(const ulonglong2*)(src + e0);
            ulonglong2 s23 = *(const ulonglong2*)(src + e0 + 2);
            ulonglong2 d01 = *(const ulonglong2*)(dst + e0);
            ulonglong2 d23 = *(const ulonglong2*)(dst + e0 + 2);
            ulonglong2 r01 = *(const ulonglong2*)(rel + e0);
            ulonglong2 r23 = *(const ulonglong2*)(rel + e0 + 2);
            s[0]=(unsigned)s01.x; s[1]=(unsigned)s01.y; s[2]=(unsigned)s23.x; s[3]=(unsigned)s23.y;
            d[0]=(unsigned)d01.x; d[1]=(unsigned)d01.y; d[2]=(unsigned)d23.x; d[3]=(unsigned)d23.y;
            r[0]=(unsigned)r01.x; r[1]=(unsigned)r01.y; r[2]=(unsigned)r23.x; r[3]=(unsigned)r23.y;
        }
        bool ok[4];
        float4 xs[4];
        #pragma unroll
        for (int j = 0; j < 4; j++) {
            ok[j] = (s[j] < nu) && (d[j] < nu) && (r[j] < (unsigned)NR);
            xs[j] = ok[j] ? g_x4[s[j]] : make_float4(0.f, 0.f, 0.f, 0.f);
        }
        #pragma unroll
        for (int j = 0; j < 4; j++)
            if (ok[j])
                red_add_v4(&g_acc1[d[j]*NR + r[j]], xs[j].x, xs[j].y, xs[j].z, 1.0f);
    } else {
        for (long long e = e0; e < ne; e++) {
            unsigned ss, dd, rr;
            if (is32) {
                const int* src = (const int*)ei;
                ss = (unsigned)src[e]; dd = (unsigned)src[ne + e];
                rr = (unsigned)((const int*)ea)[e];
            } else {
                const long long* src = (const long long*)ei;
                ss = (unsigned)src[e]; dd = (unsigned)src[ne + e];
                rr = (unsigned)((const long long*)ea)[e];
            }
            if (ss < nu && dd < nu && rr < (unsigned)NR) {
                float4 xs = g_x4[ss];
                red_add_v4(&g_acc1[dd*NR + rr], xs.x, xs.y, xs.z, 1.0f);
            }
        }
    }
}

__global__ void __launch_bounds__(256) k_edge2(const void* __restrict__ ei,
                                               const void* __restrict__ ea,
                                               int ne, int n) {
    long long e0 = (long long)(blockIdx.x * (long long)blockDim.x + threadIdx.x) * 4;
    if (e0 >= ne) return;
    const unsigned nu = (unsigned)n;
    const int is32 = g_is32;

    unsigned s[4], d[4], r[4];
    if (e0 + 4 <= ne) {
        if (is32) {
            const int* src = (const int*)ei;
            const int* dst = src + ne;
            const int* rel = (const int*)ea;
            int4 sv = *(const int4*)(src + e0);
            int4 dv = *(const int4*)(dst + e0);
            int4 rv = *(const int4*)(rel + e0);
            s[0]=(unsigned)sv.x; s[1]=(unsigned)sv.y; s[2]=(unsigned)sv.z; s[3]=(unsigned)sv.w;
            d[0]=(unsigned)dv.x; d[1]=(unsigned)dv.y; d[2]=(unsigned)dv.z; d[3]=(unsigned)dv.w;
            r[0]=(unsigned)rv.x; r[1]=(unsigned)rv.y; r[2]=(unsigned)rv.z; r[3]=(unsigned)rv.w;
        } else {
            const long long* src = (const long long*)ei;
            const long long* dst = src + ne;
            const long long* rel = (const long long*)ea;
            ulonglong2 s01 = *(const ulonglong2*)(src + e0);
            ulonglong2 s23 = *(const ulonglong2*)(src + e0 + 2);
            ulonglong2 d01 = *(const ulonglong2*)(dst + e0);
            ulonglong2 d23 = *(const ulonglong2*)(dst + e0 + 2);
            ulonglong2 r01 = *(const ulonglong2*)(rel + e0);
            ulonglong2 r23 = *(const ulonglong2*)(rel + e0 + 2);
            s[0]=(unsigned)s01.x; s[1]=(unsigned)s01.y; s[2]=(unsigned)s23.x; s[3]=(unsigned)s23.y;
            d[0]=(unsigned)d01.x; d[1]=(unsigned)d01.y; d[2]=(unsigned)d23.x; d[3]=(unsigned)d23.y;
            r[0]=(unsigned)r01.x; r[1]=(unsigned)r01.y; r[2]=(unsigned)r23.x; r[3]=(unsigned)r23.y;
        }
        bool ok[4];
        float2 hs[4];
        #pragma unroll
        for (int j = 0; j < 4; j++) {
            ok[j] = (s[j] < nu) && (d[j] < nu) && (r[j] < (unsigned)NR);
            hs[j] = ok[j] ? g_h[s[j]] : make_float2(0.f, 0.f);
        }
        #pragma unroll
        for (int j = 0; j < 4; j++)
            if (ok[j])
                red_add_v2(&g_acc2[d[j]*NR + r[j]], hs[j].x, hs[j].y);
    } else {
        for (long long e = e0; e < ne; e++) {
            unsigned ss, dd, rr;
            if (is32) {
                const int* src = (const int*)ei;
                ss = (unsigned)src[e]; dd = (unsigned)src[ne + e];
                rr = (unsigned)((const int*)ea)[e];
            } else {
                const long long* src = (const long long*)ei;
                ss = (unsigned)src[e]; dd = (unsigned)src[ne + e];
                rr = (unsigned)((const long long*)ea)[e];
            }
            if (ss < nu && dd < nu && rr < (unsigned)NR) {
                float2 hh = g_h[ss];
                red_add_v2(&g_acc2[dd*NR + rr], hh.x, hh.y);
            }
        }
    }
}

// ---- node kernels ---------------------------------------------------------

__global__ void k_node1(const float* __restrict__ W1, const float* __restrict__ root1,
                        const float* __restrict__ b1, int n) {
    int v = blockIdx.x * blockDim.x + threadIdx.x;
    if (v >= n) return;
    float4 xs = g_x4[v];
    float h0 = b1[0] + xs.x*root1[0] + xs.y*root1[2] + xs.z*root1[4];
    float h1 = b1[1] + xs.x*root1[1] + xs.y*root1[3] + xs.z*root1[5];
    #pragma unroll
    for (int r = 0; r < NR; r++) {
        float4 a = g_acc1[v*NR + r];
        float inv = 1.0f / fmaxf(a.w, 1.0f);
        float mx = a.x*inv, my = a.y*inv, mz = a.z*inv;
        h0 += mx*W1[(r*3+0)*2+0] + my*W1[(r*3+1)*2+0] + mz*W1[(r*3+2)*2+0];
        h1 += mx*W1[(r*3+0)*2+1] + my*W1[(r*3+1)*2+1] + mz*W1[(r*3+2)*2+1];
        g_inv[v*NR + r]  = inv;                       // counts for layer 2
        g_acc2[v*NR + r] = make_float2(0.f, 0.f);     // fused acc2 zeroing
    }
    g_h[v] = make_float2(fmaxf(h0, 0.f), fmaxf(h1, 0.f));
}

__global__ void k_node2(const float* __restrict__ W2, const float* __restrict__ root2,
                        const float* __restrict__ b2, float2* __restrict__ out, int n) {
    int v = blockIdx.x * blockDim.x + threadIdx.x;
    if (v >= n) return;
    float2 h = g_h[v];
    float o0 = b2[0] + h.x*root2[0] + h.y*root2[2];
    float o1 = b2[1] + h.x*root2[1] + h.y*root2[3];
    #pragma unroll
    for (int r = 0; r < NR; r++) {
        float2 s  = g_acc2[v*NR + r];
        float inv = g_inv[v*NR + r];
        float m0 = s.x*inv, m1 = s.y*inv;
        o0 += m0*W2[(r*2+0)*2+0] + m1*W2[(r*2+1)*2+0];
        o1 += m0*W2[(r*2+0)*2+1] + m1*W2[(r*2+1)*2+1];
    }
    out[v] = make_float2(o0, o1);
}

// ---- host -----------------------------------------------------------------

extern "C" void kernel_launch(void* const* d_in, const int* in_sizes, int n_in,
                              void* d_out, int out_size) {
    // Identify inputs by element count (robust to metadata ordering).
    int ix = -1, iei = -1, iea = -1, iW1 = -1, ir1 = -1, ib1 = -1,
        iW2 = -1, ir2 = -1, ib2 = -1;
    int big[3] = {-1, -1, -1};  // largest three arrays, size-descending
    for (int i = 0; i < n_in; i++) {
        int s = in_sizes[i];
        if (s == 18) iW1 = i;
        else if (s == 6)  ir1 = i;
        else if (s == 12) iW2 = i;
        else if (s == 4)  ir2 = i;
        else if (s == 2)  { if (ib1 < 0) ib1 = i; else ib2 = i; }
        else if (s > 1000) {
            int j = i;
            for (int k = 0; k < 3; k++) {
                if (big[k] < 0 || in_sizes[j] > in_sizes[big[k]]) {
                    int t = big[k]; big[k] = j; j = t;
                    if (j < 0) break;
                }
            }
        }
    }
    iei = big[0]; iea = big[1]; ix = big[2];
    if (ix < 0 || iei < 0 || iea < 0 || iW1 < 0 || ir1 < 0 || ib1 < 0 ||
        iW2 < 0 || ir2 < 0 || ib2 < 0) {   // positional fallback
        ix = 0; iei = 1; iea = 2; iW1 = 3; ir1 = 4; ib1 = 5; iW2 = 6; ir2 = 7; ib2 = 8;
    }

    const float* x     = (const float*)d_in[ix];
    const void*  ei    = d_in[iei];
    const void*  ea    = d_in[iea];
    const float* W1    = (const float*)d_in[iW1];
    const float* root1 = (const float*)d_in[ir1];
    const float* b1    = (const float*)d_in[ib1];
    const float* W2    = (const float*)d_in[iW2];
    const float* root2 = (const float*)d_in[ir2];
    const float* b2    = (const float*)d_in[ib2];

    int n  = in_sizes[ix] / 3;
    if (n > NN_MAX) n = NN_MAX;          // defensive clamp (scratch capacity)
    int ne = in_sizes[iei] / 2;

    const int threads = 256;
    int nb = (n + threads - 1) / threads;
    int et = (ne + 3) / 4;               // 4 edges per thread
    int eb = (et + threads - 1) / threads;

    k_init <<<nb, threads>>>(x, ea, n, ne);
    k_edge1<<<eb, threads>>>(ei, ea, ne, n);
    k_node1<<<nb, threads>>>(W1, root1, b1, n);
    k_edge2<<<eb, threads>>>(ei, ea, ne, n);
    k_node2<<<nb, threads>>>(W2, root2, b2, (float2*)d_out, n);
}